// round 2
// baseline (speedup 1.0000x reference)
#include <cuda_runtime.h>
#include <cuda_bf16.h>
#include <cstdint>

// Problem constants (fixed shapes for this problem instance)
#define NUM_CLASSES 1000
#define EMBED_DIM   1024
#define VEC4        (EMBED_DIM / 4)   // 256 float4 per row
#define FACTOR      0.3f
#define CAP         160               // max rows per class bucket (E[n]=32.8, sigma=5.7)

// Scratch: __device__ globals (no allocation allowed in kernel_launch)
__device__ int g_count[NUM_CLASSES];
__device__ int g_perm[NUM_CLASSES * CAP];

// K0: zero the per-class counters
__global__ void zero_counts_kernel() {
    int i = blockIdx.x * blockDim.x + threadIdx.x;
    if (i < NUM_CLASSES) g_count[i] = 0;
}

// K1: bucket rows by class. 32768 global atomics on 1000 counters -> cheap.
// NOTE: y is int32 (JAX downcasts int64 without x64 mode).
__global__ void scatter_kernel(const int* __restrict__ y, int n) {
    int i = blockIdx.x * blockDim.x + threadIdx.x;
    if (i >= n) return;
    int c = y[i];
    int pos = atomicAdd(&g_count[c], 1);
    if (pos < CAP) g_perm[c * CAP + pos] = i;
}

// K2: one CTA per class. Gather ~33 rows (4KB each, fully coalesced),
// reduce in registers, blend with centroid, write output. No atomics.
__global__ void __launch_bounds__(VEC4, 4)
sum_blend_kernel(const float* __restrict__ embed,
                 const float* __restrict__ centroid,
                 float* __restrict__ out) {
    const int c = blockIdx.x;
    const int t = threadIdx.x;            // 0..255, each thread owns 4 columns

    __shared__ int s_rows[CAP];
    __shared__ int s_n;

    if (t == 0) {
        int n = g_count[c];
        s_n = (n < CAP) ? n : CAP;
    }
    __syncthreads();
    const int n = s_n;

    // stage row indices through shared memory
    for (int r = t; r < n; r += VEC4) s_rows[r] = g_perm[c * CAP + r];
    __syncthreads();

    const float4* __restrict__ e4 = (const float4*)embed;

    float ax = 0.f, ay = 0.f, az = 0.f, aw = 0.f;

    int r = 0;
    // 4-way unroll: 4 independent 16B loads in flight per thread
    for (; r + 4 <= n; r += 4) {
        long long i0 = s_rows[r + 0];
        long long i1 = s_rows[r + 1];
        long long i2 = s_rows[r + 2];
        long long i3 = s_rows[r + 3];
        float4 v0 = e4[i0 * VEC4 + t];
        float4 v1 = e4[i1 * VEC4 + t];
        float4 v2 = e4[i2 * VEC4 + t];
        float4 v3 = e4[i3 * VEC4 + t];
        ax += v0.x + v1.x + v2.x + v3.x;
        ay += v0.y + v1.y + v2.y + v3.y;
        az += v0.z + v1.z + v2.z + v3.z;
        aw += v0.w + v1.w + v2.w + v3.w;
    }
    for (; r < n; ++r) {
        long long i0 = s_rows[r];
        float4 v0 = e4[i0 * VEC4 + t];
        ax += v0.x; ay += v0.y; az += v0.z; aw += v0.w;
    }

    // FACTOR * (sum / n) + (1 - FACTOR) * centroid
    const float inv = FACTOR / (float)n;   // n==0 -> inf; 0*inf = NaN, matches ref 0/0
    const float4 ct = ((const float4*)centroid)[c * VEC4 + t];

    float4 o;
    o.x = ax * inv + (1.0f - FACTOR) * ct.x;
    o.y = ay * inv + (1.0f - FACTOR) * ct.y;
    o.z = az * inv + (1.0f - FACTOR) * ct.z;
    o.w = aw * inv + (1.0f - FACTOR) * ct.w;
    ((float4*)out)[c * VEC4 + t] = o;
}

extern "C" void kernel_launch(void* const* d_in, const int* in_sizes, int n_in,
                              void* d_out, int out_size) {
    const float* embed    = (const float*)d_in[0];
    const int*   y        = (const int*)d_in[1];
    const float* centroid = (const float*)d_in[2];
    float*       out      = (float*)d_out;
    const int    batch    = in_sizes[1];   // 32768

    zero_counts_kernel<<<(NUM_CLASSES + 255) / 256, 256>>>();
    scatter_kernel<<<(batch + 511) / 512, 512>>>(y, batch);
    sum_blend_kernel<<<NUM_CLASSES, VEC4>>>(embed, centroid, out);
}